// round 1
// baseline (speedup 1.0000x reference)
#include <cuda_runtime.h>

#define CROP 14
#define B_ 4
#define N_ 256
#define H_ 256
#define W_ 256
#define C_ 256

__global__ __launch_bounds__(256) void roi_align_kernel(
    const float* __restrict__ boxes,
    const float* __restrict__ fpn,
    float* __restrict__ out)
{
    // Per-box sampling grids (y and x axes)
    __shared__ int   s_i0[2][CROP];
    __shared__ int   s_i1[2][CROP];
    __shared__ float s_w [2][CROP];
    __shared__ float s_v [2][CROP];

    const int blk = blockIdx.x;        // b * N_ + n
    const int b   = blk >> 8;          // N_ = 256

    // boxes layout: [B, N, 4] = (x1, y1, x2, y2)
    const float4 bx = ((const float4*)boxes)[blk];

    const int tid = threadIdx.x;
    if (tid < 2 * CROP) {
        const int axis = tid / CROP;   // 0 = y, 1 = x
        const int i    = tid % CROP;
        const float lo = (axis == 0) ? bx.y : bx.x;   // y1 or x1
        const float hi = (axis == 0) ? bx.w : bx.z;   // y2 or x2
        // Replicate reference math in float32:
        //   n1 = lo/255 ; n2 = (hi-1)/255 ; t = i/13 ; s = (n1 + (n2-n1)*t) * 255
        const float t  = (float)i / 13.0f;
        const float n1 = lo / 255.0f;
        const float n2 = (hi - 1.0f) / 255.0f;
        const float s  = (n1 + (n2 - n1) * t) * 255.0f;
        const float valid = (s >= 0.0f && s <= 255.0f) ? 1.0f : 0.0f;
        const float f0 = floorf(s);
        const float w  = s - f0;
        int i0 = (int)f0;
        int i1 = i0 + 1;
        i0 = min(max(i0, 0), H_ - 1);
        i1 = min(max(i1, 0), H_ - 1);
        s_i0[axis][i] = i0;
        s_i1[axis][i] = i1;
        s_w [axis][i] = w;
        s_v [axis][i] = valid;
    }
    __syncthreads();

    const float4* img  = (const float4*)(fpn) + (size_t)b * (H_ * W_ * (C_ / 4));
    float4*       outp = (float4*)(out) + (size_t)blk * (CROP * CROP) * (C_ / 4);

    const int sub = tid >> 6;   // which of 4 crop positions this iteration
    const int q   = tid & 63;   // float4 index within C=256 channels

    #pragma unroll 2
    for (int pb = 0; pb < CROP * CROP; pb += 4) {
        const int pos = pb + sub;
        const int py  = pos / CROP;
        const int px  = pos - py * CROP;

        const int   y0 = s_i0[0][py], y1 = s_i1[0][py];
        const int   x0 = s_i0[1][px], x1 = s_i1[1][px];
        const float wy = s_w[0][py],  wx = s_w[1][px];
        const float v  = s_v[0][py] * s_v[1][px];

        const float4 tl = img[(y0 * W_ + x0) * (C_ / 4) + q];
        const float4 tr = img[(y0 * W_ + x1) * (C_ / 4) + q];
        const float4 bl = img[(y1 * W_ + x0) * (C_ / 4) + q];
        const float4 br = img[(y1 * W_ + x1) * (C_ / 4) + q];

        const float w00 = (1.0f - wy) * (1.0f - wx) * v;
        const float w01 = (1.0f - wy) * wx * v;
        const float w10 = wy * (1.0f - wx) * v;
        const float w11 = wy * wx * v;

        float4 r;
        r.x = tl.x * w00 + tr.x * w01 + bl.x * w10 + br.x * w11;
        r.y = tl.y * w00 + tr.y * w01 + bl.y * w10 + br.y * w11;
        r.z = tl.z * w00 + tr.z * w01 + bl.z * w10 + br.z * w11;
        r.w = tl.w * w00 + tr.w * w01 + bl.w * w10 + br.w * w11;

        outp[pos * (C_ / 4) + q] = r;
    }
}

extern "C" void kernel_launch(void* const* d_in, const int* in_sizes, int n_in,
                              void* d_out, int out_size) {
    // metadata order should be (boxes, fpn); pick by size defensively.
    const float* boxes = (const float*)d_in[0];
    const float* fpn   = (const float*)d_in[1];
    if (n_in >= 2 && in_sizes[0] > in_sizes[1]) {
        boxes = (const float*)d_in[1];
        fpn   = (const float*)d_in[0];
    }
    roi_align_kernel<<<B_ * N_, 256>>>(boxes, fpn, (float*)d_out);
}

// round 2
// speedup vs baseline: 1.4645x; 1.4645x over previous
#include <cuda_runtime.h>

#define CROP 14
#define B_ 4
#define N_ 256
#define H_ 256
#define W_ 256
#define C_ 256

// 196 positions per box, split across 7 CTAs of 28 positions each.
#define PARTS 7
#define POS_PER_PART 28

__global__ __launch_bounds__(256) void roi_align_kernel(
    const float* __restrict__ boxes,
    const float* __restrict__ fpn,
    float* __restrict__ out)
{
    // Per-box sampling grids (y and x axes)
    __shared__ int   s_i0[2][CROP];
    __shared__ int   s_i1[2][CROP];
    __shared__ float s_w [2][CROP];
    __shared__ float s_v [2][CROP];

    const int blk  = blockIdx.y;       // box index: b * N_ + n  (box-major bid order)
    const int part = blockIdx.x;       // 0..6, which 28-position slice
    const int b    = blk >> 8;         // N_ = 256

    // boxes layout: [B, N, 4] = (x1, y1, x2, y2)
    const float4 bx = ((const float4*)boxes)[blk];

    const int tid = threadIdx.x;
    if (tid < 2 * CROP) {
        const int axis = tid / CROP;   // 0 = y, 1 = x
        const int i    = tid % CROP;
        const float lo = (axis == 0) ? bx.y : bx.x;   // y1 or x1
        const float hi = (axis == 0) ? bx.w : bx.z;   // y2 or x2
        // Replicate reference math in float32:
        //   n1 = lo/255 ; n2 = (hi-1)/255 ; t = i/13 ; s = (n1 + (n2-n1)*t) * 255
        const float t  = (float)i / 13.0f;
        const float n1 = lo / 255.0f;
        const float n2 = (hi - 1.0f) / 255.0f;
        const float s  = (n1 + (n2 - n1) * t) * 255.0f;
        const float valid = (s >= 0.0f && s <= 255.0f) ? 1.0f : 0.0f;
        const float f0 = floorf(s);
        const float w  = s - f0;
        int i0 = (int)f0;
        int i1 = i0 + 1;
        i0 = min(max(i0, 0), H_ - 1);
        i1 = min(max(i1, 0), H_ - 1);
        s_i0[axis][i] = i0;
        s_i1[axis][i] = i1;
        s_w [axis][i] = w;
        s_v [axis][i] = valid;
    }
    __syncthreads();

    const float4* img  = (const float4*)(fpn) + (size_t)b * (H_ * W_ * (C_ / 4));
    float4*       outp = (float4*)(out) + (size_t)blk * (CROP * CROP) * (C_ / 4);

    const int sub  = tid >> 6;   // which of 4 crop positions this iteration
    const int q    = tid & 63;   // float4 index within C=256 channels
    const int base = part * POS_PER_PART;

    #pragma unroll 2
    for (int pb = 0; pb < POS_PER_PART; pb += 4) {
        const int pos = base + pb + sub;
        const int py  = pos / CROP;
        const int px  = pos - py * CROP;

        const int   y0 = s_i0[0][py], y1 = s_i1[0][py];
        const int   x0 = s_i0[1][px], x1 = s_i1[1][px];
        const float wy = s_w[0][py],  wx = s_w[1][px];
        const float v  = s_v[0][py] * s_v[1][px];

        const float4 tl = img[(y0 * W_ + x0) * (C_ / 4) + q];
        const float4 tr = img[(y0 * W_ + x1) * (C_ / 4) + q];
        const float4 bl = img[(y1 * W_ + x0) * (C_ / 4) + q];
        const float4 br = img[(y1 * W_ + x1) * (C_ / 4) + q];

        const float w00 = (1.0f - wy) * (1.0f - wx) * v;
        const float w01 = (1.0f - wy) * wx * v;
        const float w10 = wy * (1.0f - wx) * v;
        const float w11 = wy * wx * v;

        float4 r;
        r.x = tl.x * w00 + tr.x * w01 + bl.x * w10 + br.x * w11;
        r.y = tl.y * w00 + tr.y * w01 + bl.y * w10 + br.y * w11;
        r.z = tl.z * w00 + tr.z * w01 + bl.z * w10 + br.z * w11;
        r.w = tl.w * w00 + tr.w * w01 + bl.w * w10 + br.w * w11;

        // Streaming store: output is never re-read; keep it out of L2 so the
        // current batch image stays resident.
        __stcs(&outp[pos * (C_ / 4) + q], r);
    }
}

extern "C" void kernel_launch(void* const* d_in, const int* in_sizes, int n_in,
                              void* d_out, int out_size) {
    const float* boxes = (const float*)d_in[0];
    const float* fpn   = (const float*)d_in[1];
    if (n_in >= 2 && in_sizes[0] > in_sizes[1]) {
        boxes = (const float*)d_in[1];
        fpn   = (const float*)d_in[0];
    }
    dim3 grid(PARTS, B_ * N_);
    roi_align_kernel<<<grid, 256>>>(boxes, fpn, (float*)d_out);
}